// round 6
// baseline (speedup 1.0000x reference)
#include <cuda_runtime.h>
#include <cuda_fp16.h>
#include <cstdint>

#define NRES  1024
#define CDIM  384
#define NH    12
#define CHD   32
#define NPTS  4
#define PDIM  144
#define DPAIR 128
#define FDIM  48            // 32 scalar + 12 point dims + 4 pad
#define WPROJ 1440          // 384*3 + 144*2
#define SCALEF 0.17677669529663687f
#define NN    (NRES * NRES)
#define MSPLIT 16

// ---------------- scratch (device globals: allocation-free) ----------------
__device__ float g_Wall[CDIM * WPROJ];
__device__ float g_ball[WPROJ];
__device__ float g_proj[NRES * WPROJ];
__device__ float g_Fq[NH * NRES * FDIM];
__device__ float g_Fk[NH * NRES * FDIM];
__device__ float g_Vs[NH * NRES * CHD];
__device__ float g_rowt[NH * NRES];
__device__ float g_colt[NH * NRES];
__device__ float g_pM[MSPLIT * NH * NRES];
__device__ float g_pS[MSPLIT * NH * NRES];
__device__ float g_pO[(size_t)MSPLIT * NH * NRES * CHD];   // 25 MB
__device__ float g_wt[NRES * CDIM];
__device__ float g_x[NRES * CDIM];

// ---------------- helpers ----------------
__device__ __forceinline__ uint32_t f2tf(float x) {
    uint32_t u;
    asm("cvt.rna.tf32.f32 %0, %1;" : "=r"(u) : "f"(x));
    return u;
}

__device__ __forceinline__ void mma8(float c[4],
                                     uint32_t a0, uint32_t a1, uint32_t a2, uint32_t a3,
                                     uint32_t b0, uint32_t b1) {
    asm volatile(
        "mma.sync.aligned.m16n8k8.row.col.f32.tf32.tf32.f32 "
        "{%0,%1,%2,%3}, {%4,%5,%6,%7}, {%8,%9}, {%0,%1,%2,%3};"
        : "+f"(c[0]), "+f"(c[1]), "+f"(c[2]), "+f"(c[3])
        : "r"(a0), "r"(a1), "r"(a2), "r"(a3), "r"(b0), "r"(b1));
}

__device__ __forceinline__ void cp16(uint32_t sa, const void* g) {
    asm volatile("cp.async.cg.shared.global [%0], [%1], 16;" :: "r"(sa), "l"(g));
}

// ---------------- K0: pack projection weights [384 x 1440] ----------------
__global__ void k_pack(const float* __restrict__ Wq, const float* __restrict__ Wk,
                       const float* __restrict__ Wv, const float* __restrict__ Wpq,
                       const float* __restrict__ Wpk,
                       const float* __restrict__ bq, const float* __restrict__ bk,
                       const float* __restrict__ bv, const float* __restrict__ bpq,
                       const float* __restrict__ bpk) {
    int i = blockIdx.x * 256 + threadIdx.x;
    if (i < CDIM * WPROJ) {
        int k = i / WPROJ, j = i % WPROJ;
        float v;
        if (j < 384)       v = Wq[k * 384 + j];
        else if (j < 768)  v = Wk[k * 384 + (j - 384)];
        else if (j < 1152) v = Wv[k * 384 + (j - 768)];
        else if (j < 1296) v = Wpq[k * 144 + (j - 1152)];
        else               v = Wpk[k * 144 + (j - 1296)];
        g_Wall[i] = v;
    }
    if (i < WPROJ) {
        float b;
        if (i < 384)       b = bq[i];
        else if (i < 768)  b = bk[i - 384];
        else if (i < 1152) b = bv[i - 768];
        else if (i < 1296) b = bpq[i - 1152];
        else               b = bpk[i - 1296];
        g_ball[i] = b;
    }
}

// ---------------- generic tf32 GEMM: C = A[MxK] @ B[KxN] + bias (+resid) ----
__global__ void __launch_bounds__(256) k_gemm(
    const float* __restrict__ A, const float* __restrict__ B,
    const float* __restrict__ bias, const float* __restrict__ resid,
    float* __restrict__ out, int M, int Nn, int K) {
    __shared__ float As[64 * 36];
    __shared__ float Bs[32 * 72];
    int tid = threadIdx.x;
    int lane = tid & 31, wid = tid >> 5;
    int wy = wid >> 1, wx = wid & 1;
    int g = lane >> 2, t = lane & 3;
    int n0 = blockIdx.x * 64, m0 = blockIdx.y * 64;

    float c[4][4];
#pragma unroll
    for (int i = 0; i < 4; i++)
#pragma unroll
        for (int j = 0; j < 4; j++) c[i][j] = 0.f;

    for (int kc = 0; kc < K; kc += 32) {
#pragma unroll
        for (int it = 0; it < 2; it++) {
            int idx = tid + it * 256;
            int r = idx >> 3, c4 = (idx & 7) * 4;
            float4 v = *(const float4*)(A + (size_t)(m0 + r) * K + kc + c4);
            *(float4*)(As + r * 36 + c4) = v;
        }
#pragma unroll
        for (int it = 0; it < 2; it++) {
            int idx = tid + it * 256;
            int r = idx >> 4, c4 = (idx & 15) * 4;
            int col = n0 + c4;
            float4 v = make_float4(0.f, 0.f, 0.f, 0.f);
            if (col < Nn) v = *(const float4*)(B + (size_t)(kc + r) * Nn + col);
            *(float4*)(Bs + r * 72 + c4) = v;
        }
        __syncthreads();
#pragma unroll
        for (int ks = 0; ks < 4; ks++) {
            uint32_t a0 = f2tf(As[(wy * 16 + g) * 36 + ks * 8 + t]);
            uint32_t a1 = f2tf(As[(wy * 16 + g + 8) * 36 + ks * 8 + t]);
            uint32_t a2 = f2tf(As[(wy * 16 + g) * 36 + ks * 8 + t + 4]);
            uint32_t a3 = f2tf(As[(wy * 16 + g + 8) * 36 + ks * 8 + t + 4]);
#pragma unroll
            for (int nb = 0; nb < 4; nb++) {
                uint32_t b0 = f2tf(Bs[(ks * 8 + t) * 72 + wx * 32 + nb * 8 + g]);
                uint32_t b1 = f2tf(Bs[(ks * 8 + t + 4) * 72 + wx * 32 + nb * 8 + g]);
                mma8(c[nb], a0, a1, a2, a3, b0, b1);
            }
        }
        __syncthreads();
    }
#pragma unroll
    for (int nb = 0; nb < 4; nb++)
#pragma unroll
        for (int rr = 0; rr < 4; rr++) {
            int row = m0 + wy * 16 + g + ((rr & 2) ? 8 : 0);
            int col = n0 + wx * 32 + nb * 8 + 2 * t + (rr & 1);
            if (col < Nn) {
                float v = c[nb][rr] + bias[col];
                if (resid) v += resid[(size_t)row * Nn + col];
                out[(size_t)row * Nn + col] = v;
            }
        }
}

// ---------------- K1b: rotate points, build per-head features ----------------
__global__ void k_feat(const float* __restrict__ rot) {
    int n = blockIdx.x;
    int t = threadIdx.x;  // 128 threads
    __shared__ float R[9];
    __shared__ float sq[NH], sk[NH];
    if (t < 9)  R[t] = rot[n * 9 + t];
    if (t < NH) { sq[t] = 0.f; sk[t] = 0.f; }
    __syncthreads();
    const float* pr = g_proj + (size_t)n * WPROJ;
    for (int idx = t; idx < PDIM; idx += 128) {
        int h = idx / 12, rem = idx % 12, p = rem / 3, j = rem % 3;
        const float* pq = pr + 1152 + (h * NPTS + p) * 3;
        const float* pk = pr + 1296 + (h * NPTS + p) * 3;
        float qg = pq[0] * R[j] + pq[1] * R[3 + j] + pq[2] * R[6 + j];
        float kg = pk[0] * R[j] + pk[1] * R[3 + j] + pk[2] * R[6 + j];
        g_Fq[((size_t)h * NRES + n) * FDIM + 32 + p * 3 + j] = qg;
        g_Fk[((size_t)h * NRES + n) * FDIM + 32 + p * 3 + j] = kg;
        atomicAdd(&sq[h], qg * qg);
        atomicAdd(&sk[h], kg * kg);
    }
    for (int c = t; c < CDIM; c += 128) {
        int h = c >> 5, cc = c & 31;
        g_Fq[((size_t)h * NRES + n) * FDIM + cc] = pr[c];
        g_Fk[((size_t)h * NRES + n) * FDIM + cc] = pr[384 + c];
        g_Vs[((size_t)h * NRES + n) * CHD + cc] = pr[768 + c];
    }
    if (t < NH * 4) {
        int h = t >> 2;
        g_Fq[((size_t)h * NRES + n) * FDIM + 44 + (t & 3)] = 0.f;
        g_Fk[((size_t)h * NRES + n) * FDIM + 44 + (t & 3)] = 0.f;
    }
    __syncthreads();
    if (t < NH) {
        g_rowt[t * NRES + n] = sq[t];
        g_colt[t * NRES + n] = sk[t];
    }
}

// ================= K2: FUSED pair-bias + attention ==========================
// grid (16 m-chunks, 16 n-tiles), 256 threads. Each block:
//   phase 1: stream pair[n0:n0+64, m0:m0+64, :128] (2 MB) -> bias smem (fp16)
//   phase 2: two 128-thread groups, 6 heads each: S-mma + softmax + PV,
//            single 64-col tile -> unnormalized partials (M,S,O) per head.
#define SBIAS_BYTES (NH * 64 * 64 * 2)                 // 98304
#define GRPBUF_FLOATS (64*52 + 64*40 + 4*16*68 + 64)   // 10304
#define FUSED_SMEM (SBIAS_BYTES + 2 * GRPBUF_FLOATS * 4)
__global__ void __launch_bounds__(256) k_fused(
    const float* __restrict__ pair, const float* __restrict__ Wp,
    const float* __restrict__ bp) {
    extern __shared__ char smem[];
    __half* sbias = (__half*)smem;                        // [h][n 64][m 64]
    float* pairbuf = (float*)(smem + SBIAS_BYTES);        // 2 x [64][128] (phase 1)
    int tid = threadIdx.x, lane = tid & 31, w = tid >> 5;
    int g = lane >> 2, t = lane & 3;
    int m0 = blockIdx.x * 64;
    int n0 = blockIdx.y * 64;
    int sp = blockIdx.x;

    // ---- phase 1: bias GEMM into smem ----
    {
        // Wpair fragments (warps 0-3 compute)
        uint32_t bf[16][4];
        float bpv[2][2];
        if (w < 4) {
#pragma unroll
            for (int ks = 0; ks < 16; ks++)
#pragma unroll
                for (int nb = 0; nb < 2; nb++) {
                    int h = nb * 8 + g;
                    float b0 = (h < 12) ? Wp[(ks * 8 + t) * 12 + h] : 0.f;
                    float b1 = (h < 12) ? Wp[(ks * 8 + t + 4) * 12 + h] : 0.f;
                    bf[ks][nb * 2 + 0] = f2tf(b0);
                    bf[ks][nb * 2 + 1] = f2tf(b1);
                }
#pragma unroll
            for (int nb = 0; nb < 2; nb++)
#pragma unroll
                for (int par = 0; par < 2; par++) {
                    int h = nb * 8 + 2 * t + par;
                    bpv[nb][par] = (h < 12) ? bp[h] : 0.f;
                }
        }

        auto stage = [&](int i, int buf) {
            const float4* src = (const float4*)(pair +
                ((size_t)(n0 + i) * NRES + m0) * DPAIR);
            float* dst = pairbuf + buf * (64 * 128);
#pragma unroll
            for (int it = 0; it < 8; it++) {
                int idx = tid + it * 256;
                int r = idx >> 5, c4 = idx & 31;
                uint32_t sa = (uint32_t)__cvta_generic_to_shared(
                    dst + r * 128 + ((c4 ^ (r & 7)) << 2));
                cp16(sa, src + idx);
            }
            asm volatile("cp.async.commit_group;");
        };

        stage(0, 0);
        int rbase = (w & 3) * 16;
        for (int i = 0; i < 64; i++) {
            if (i + 1 < 64) {
                stage(i + 1, (i + 1) & 1);
                asm volatile("cp.async.wait_group 1;");
            } else {
                asm volatile("cp.async.wait_group 0;");
            }
            __syncthreads();
            if (w < 4) {
                const float* P = pairbuf + (i & 1) * (64 * 128);
                float c[2][4];
#pragma unroll
                for (int a = 0; a < 2; a++)
#pragma unroll
                    for (int b = 0; b < 4; b++) c[a][b] = 0.f;
#pragma unroll
                for (int ks = 0; ks < 16; ks++) {
                    const float* r0p = P + (rbase + g) * 128;
                    const float* r8p = P + (rbase + g + 8) * 128;
                    int e0 = (((2 * ks) ^ g) << 2) + t;
                    int e1 = (((2 * ks + 1) ^ g) << 2) + t;
                    uint32_t a0 = f2tf(r0p[e0]);
                    uint32_t a1 = f2tf(r8p[e0]);
                    uint32_t a2 = f2tf(r0p[e1]);
                    uint32_t a3 = f2tf(r8p[e1]);
                    mma8(c[0], a0, a1, a2, a3, bf[ks][0], bf[ks][1]);
                    mma8(c[1], a0, a1, a2, a3, bf[ks][2], bf[ks][3]);
                }
#pragma unroll
                for (int nb = 0; nb < 2; nb++)
#pragma unroll
                    for (int rr = 0; rr < 4; rr++) {
                        int h = nb * 8 + 2 * t + (rr & 1);
                        if (h < 12) {
                            int mloc = rbase + g + ((rr & 2) ? 8 : 0);
                            sbias[(h * 64 + i) * 64 + mloc] =
                                __float2half(c[nb][rr] + bpv[nb][rr & 1]);
                        }
                    }
            }
            __syncthreads();
        }
    }
    __syncthreads();

    // ---- phase 2: attention, 2 groups x 6 heads ----
    int grp = tid >> 7, ltid = tid & 127, w4 = (tid >> 5) & 3;
    float* gb = (float*)(smem + SBIAS_BYTES) + grp * GRPBUF_FLOATS;
    float* Fks = gb;                       // 64 x 52
    float* Vsm = Fks + 64 * 52;            // 64 x 40
    float* Psm = Vsm + 64 * 40;            // 4 x 16 x 68
    float* cts = Psm + 4 * 16 * 68;        // 64
    float* Pw = Psm + w4 * (16 * 68);
    int ln0 = w4 * 16 + g;                 // local n row
    int ln8 = ln0 + 8;
    int row0 = n0 + ln0, row8 = n0 + ln8;

    for (int hh = 0; hh < 6; hh++) {
        int h = grp * 6 + hh;
        // load Fq fragments for this head
        uint32_t afr[6][4];
#pragma unroll
        for (int ks = 0; ks < 6; ks++) {
            afr[ks][0] = f2tf(g_Fq[((size_t)h * NRES + row0) * FDIM + ks * 8 + t]);
            afr[ks][1] = f2tf(g_Fq[((size_t)h * NRES + row8) * FDIM + ks * 8 + t]);
            afr[ks][2] = f2tf(g_Fq[((size_t)h * NRES + row0) * FDIM + ks * 8 + t + 4]);
            afr[ks][3] = f2tf(g_Fq[((size_t)h * NRES + row8) * FDIM + ks * 8 + t + 4]);
        }
        float rt0 = -0.5f * SCALEF * g_rowt[h * NRES + row0];
        float rt8 = -0.5f * SCALEF * g_rowt[h * NRES + row8];

        // stage Fk, V, cts for this head / m-chunk
#pragma unroll
        for (int it = 0; it < 6; it++) {
            int idx = ltid + it * 128;
            int r = idx / 12, c4 = (idx % 12) * 4;
            float4 v = *(const float4*)(g_Fk + ((size_t)h * NRES + m0 + r) * FDIM + c4);
            uint4 u = make_uint4(f2tf(v.x), f2tf(v.y), f2tf(v.z), f2tf(v.w));
            *(uint4*)(Fks + r * 52 + c4) = u;
        }
#pragma unroll
        for (int it = 0; it < 4; it++) {
            int idx = ltid + it * 128;
            int r = idx >> 3, c4 = (idx & 7) * 4;
            float4 v = *(const float4*)(g_Vs + ((size_t)h * NRES + m0 + r) * CHD + c4);
            uint4 u = make_uint4(f2tf(v.x), f2tf(v.y), f2tf(v.z), f2tf(v.w));
            *(uint4*)(Vsm + r * 40 + c4) = u;
        }
        if (ltid < 64) cts[ltid] = -0.5f * SCALEF * g_colt[h * NRES + m0 + ltid];
        asm volatile("bar.sync %0, 128;" :: "r"(1 + grp));

        // S = Fq @ Fk^T (16 x 64 per warp)
        float s[8][4];
#pragma unroll
        for (int nb = 0; nb < 8; nb++) {
#pragma unroll
            for (int j = 0; j < 4; j++) s[nb][j] = 0.f;
#pragma unroll
            for (int ks = 0; ks < 6; ks++) {
                uint32_t b0 = __float_as_uint(Fks[(nb * 8 + g) * 52 + ks * 8 + t]);
                uint32_t b1 = __float_as_uint(Fks[(nb * 8 + g) * 52 + ks * 8 + t + 4]);
                mma8(s[nb], afr[ks][0], afr[ks][1], afr[ks][2], afr[ks][3], b0, b1);
            }
        }
        // logits: + bias (smem fp16) + colt + rowt
        const __half2* bh0 = (const __half2*)(sbias + (h * 64 + ln0) * 64);
        const __half2* bh8 = (const __half2*)(sbias + (h * 64 + ln8) * 64);
#pragma unroll
        for (int nb = 0; nb < 8; nb++) {
            int cA = nb * 8 + 2 * t;
            float2 b0f = __half22float2(bh0[cA >> 1]);
            float2 b8f = __half22float2(bh8[cA >> 1]);
            s[nb][0] = SCALEF * s[nb][0] + rt0 + cts[cA]     + b0f.x;
            s[nb][1] = SCALEF * s[nb][1] + rt0 + cts[cA + 1] + b0f.y;
            s[nb][2] = SCALEF * s[nb][2] + rt8 + cts[cA]     + b8f.x;
            s[nb][3] = SCALEF * s[nb][3] + rt8 + cts[cA + 1] + b8f.y;
        }
        // single-tile softmax (exact)
        float M0 = -1e30f, M8 = -1e30f;
#pragma unroll
        for (int nb = 0; nb < 8; nb++) {
            M0 = fmaxf(M0, fmaxf(s[nb][0], s[nb][1]));
            M8 = fmaxf(M8, fmaxf(s[nb][2], s[nb][3]));
        }
        M0 = fmaxf(M0, __shfl_xor_sync(0xffffffffu, M0, 1));
        M0 = fmaxf(M0, __shfl_xor_sync(0xffffffffu, M0, 2));
        M8 = fmaxf(M8, __shfl_xor_sync(0xffffffffu, M8, 1));
        M8 = fmaxf(M8, __shfl_xor_sync(0xffffffffu, M8, 2));

        float S0 = 0.f, S8 = 0.f;
#pragma unroll
        for (int nb = 0; nb < 8; nb++) {
            int cA = nb * 8 + 2 * t, cB = cA + 1;
            float p00 = __expf(s[nb][0] - M0);
            float p01 = __expf(s[nb][1] - M0);
            float p10 = __expf(s[nb][2] - M8);
            float p11 = __expf(s[nb][3] - M8);
            S0 += p00 + p01; S8 += p10 + p11;
            Pw[g * 68 + cA] = __uint_as_float(f2tf(p00));
            Pw[g * 68 + cB] = __uint_as_float(f2tf(p01));
            Pw[(g + 8) * 68 + cA] = __uint_as_float(f2tf(p10));
            Pw[(g + 8) * 68 + cB] = __uint_as_float(f2tf(p11));
        }
        S0 += __shfl_xor_sync(0xffffffffu, S0, 1);
        S0 += __shfl_xor_sync(0xffffffffu, S0, 2);
        S8 += __shfl_xor_sync(0xffffffffu, S8, 1);
        S8 += __shfl_xor_sync(0xffffffffu, S8, 2);
        __syncwarp();

        // O = P @ V
        float o[4][4];
#pragma unroll
        for (int a = 0; a < 4; a++)
#pragma unroll
            for (int b = 0; b < 4; b++) o[a][b] = 0.f;
#pragma unroll
        for (int ks = 0; ks < 8; ks++) {
            uint32_t a0 = __float_as_uint(Pw[g * 68 + ks * 8 + t]);
            uint32_t a1 = __float_as_uint(Pw[(g + 8) * 68 + ks * 8 + t]);
            uint32_t a2 = __float_as_uint(Pw[g * 68 + ks * 8 + t + 4]);
            uint32_t a3 = __float_as_uint(Pw[(g + 8) * 68 + ks * 8 + t + 4]);
#pragma unroll
            for (int nb = 0; nb < 4; nb++) {
                uint32_t b0 = __float_as_uint(Vsm[(ks * 8 + t) * 40 + nb * 8 + g]);
                uint32_t b1 = __float_as_uint(Vsm[(ks * 8 + t + 4) * 40 + nb * 8 + g]);
                mma8(o[nb], a0, a1, a2, a3, b0, b1);
            }
        }

        // write unnormalized partials
        int pidx0 = (sp * NH + h) * NRES + row0;
        int pidx8 = pidx0 + 8;
        if (t == 0) {
            g_pM[pidx0] = M0; g_pS[pidx0] = S0;
            g_pM[pidx8] = M8; g_pS[pidx8] = S8;
        }
#pragma unroll
        for (int nb = 0; nb < 4; nb++) {
            int c0 = nb * 8 + 2 * t;
            g_pO[(size_t)pidx0 * CHD + c0]     = o[nb][0];
            g_pO[(size_t)pidx0 * CHD + c0 + 1] = o[nb][1];
            g_pO[(size_t)pidx8 * CHD + c0]     = o[nb][2];
            g_pO[(size_t)pidx8 * CHD + c0 + 1] = o[nb][3];
        }
        asm volatile("bar.sync %0, 128;" :: "r"(1 + grp));
    }
}

// ---------------- K3: merge m-split partials -------------------------------
__global__ void __launch_bounds__(256) k_merge() {
    int w = threadIdx.x >> 5, lane = threadIdx.x & 31;
    int pi = blockIdx.x * 8 + w;           // 12288 (n,h) pairs
    int n = pi / NH, h = pi % NH;
    float Ms[MSPLIT], Ss[MSPLIT], Os[MSPLIT];
    float Mx = -1e30f;
#pragma unroll
    for (int s = 0; s < MSPLIT; s++) {
        int idx = (s * NH + h) * NRES + n;
        Ms[s] = g_pM[idx];
        Ss[s] = g_pS[idx];
        Os[s] = g_pO[(size_t)idx * CHD + lane];
        Mx = fmaxf(Mx, Ms[s]);
    }
    float den = 0.f, num = 0.f;
#pragma unroll
    for (int s = 0; s < MSPLIT; s++) {
        float wgt = __expf(Ms[s] - Mx);
        den += wgt * Ss[s];
        num += wgt * Os[s];
    }
    g_wt[(size_t)n * CDIM + h * 32 + lane] = num / den;
}

// ---------------- K4b: layernorm ----------------
__global__ void k_ln(const float* __restrict__ gamma, const float* __restrict__ beta,
                     float* __restrict__ out) {
    int n = blockIdx.x, t = threadIdx.x;  // 128 threads
    int lane = t & 31, w = t >> 5;
    __shared__ float r1[4], r2[4];
    const float* x = g_x + (size_t)n * CDIM;
    float v0 = x[t], v1 = x[t + 128], v2 = x[t + 256];
    float s = v0 + v1 + v2;
#pragma unroll
    for (int off = 16; off; off >>= 1) s += __shfl_xor_sync(0xffffffffu, s, off);
    if (lane == 0) r1[w] = s;
    __syncthreads();
    float mean = (r1[0] + r1[1] + r1[2] + r1[3]) * (1.f / CDIM);
    float d0 = v0 - mean, d1 = v1 - mean, d2 = v2 - mean;
    float ss = d0 * d0 + d1 * d1 + d2 * d2;
#pragma unroll
    for (int off = 16; off; off >>= 1) ss += __shfl_xor_sync(0xffffffffu, ss, off);
    if (lane == 0) r2[w] = ss;
    __syncthreads();
    float var = (r2[0] + r2[1] + r2[2] + r2[3]) * (1.f / CDIM);
    float rs = rsqrtf(var + 1e-5f);
    out[(size_t)n * CDIM + t]       = d0 * rs * gamma[t] + beta[t];
    out[(size_t)n * CDIM + t + 128] = d1 * rs * gamma[t + 128] + beta[t + 128];
    out[(size_t)n * CDIM + t + 256] = d2 * rs * gamma[t + 256] + beta[t + 256];
}

// ---------------- launch (single stream — graph-capture safe) ----------------
extern "C" void kernel_launch(void* const* d_in, const int* in_sizes, int n_in,
                              void* d_out, int out_size) {
    (void)in_sizes; (void)n_in; (void)out_size;
    const float* single = (const float*)d_in[0];
    const float* pair   = (const float*)d_in[1];
    const float* rot    = (const float*)d_in[2];
    const float* Wq  = (const float*)d_in[4];
    const float* bq  = (const float*)d_in[5];
    const float* Wk  = (const float*)d_in[6];
    const float* bk  = (const float*)d_in[7];
    const float* Wv  = (const float*)d_in[8];
    const float* bv  = (const float*)d_in[9];
    const float* Wpair = (const float*)d_in[10];
    const float* bpair = (const float*)d_in[11];
    const float* Wpq = (const float*)d_in[12];
    const float* bpq = (const float*)d_in[13];
    const float* Wpk = (const float*)d_in[14];
    const float* bpk = (const float*)d_in[15];
    const float* Wout = (const float*)d_in[16];
    const float* bout = (const float*)d_in[17];
    const float* gamma = (const float*)d_in[18];
    const float* beta  = (const float*)d_in[19];

    float *pWall, *pball, *pproj, *pwt, *px;
    cudaGetSymbolAddress((void**)&pWall, g_Wall);
    cudaGetSymbolAddress((void**)&pball, g_ball);
    cudaGetSymbolAddress((void**)&pproj, g_proj);
    cudaGetSymbolAddress((void**)&pwt,   g_wt);
    cudaGetSymbolAddress((void**)&px,    g_x);

    static bool attr_done = false;
    if (!attr_done) {
        cudaFuncSetAttribute(k_fused,
            cudaFuncAttributeMaxDynamicSharedMemorySize, FUSED_SMEM);
        attr_done = true;
    }

    // K0: pack weights
    k_pack<<<2160, 256>>>(Wq, Wk, Wv, Wpq, Wpk, bq, bk, bv, bpq, bpk);
    // K1: projections [1024 x 1440]
    k_gemm<<<dim3(23, 16), 256>>>(single, pWall, pball, nullptr, pproj,
                                  NRES, WPROJ, CDIM);
    // K1b: rotations + features
    k_feat<<<NRES, 128>>>(rot);
    // K2: fused pair-bias + attention (the 512 MB stream)
    k_fused<<<dim3(16, 16), 256, FUSED_SMEM>>>(pair, Wpair, bpair);
    // K3: merge partials
    k_merge<<<NRES * NH / 8, 256>>>();
    // K4a: out projection + residual
    k_gemm<<<dim3(6, 16), 256>>>(pwt, Wout, bout, single, px, NRES, CDIM, CDIM);
    // K4b: layernorm -> output
    k_ln<<<NRES, 128>>>(gamma, beta, (float*)d_out);
}

// round 7
// speedup vs baseline: 1.2695x; 1.2695x over previous
#include <cuda_runtime.h>
#include <cuda_fp16.h>
#include <cstdint>

#define NRES  1024
#define CDIM  384
#define NH    12
#define CHD   32
#define NPTS  4
#define PDIM  144
#define DPAIR 128
#define FDIM  48            // 32 scalar + 12 point dims + 4 pad
#define WPROJ 1440          // 384*3 + 144*2
#define SCALEF 0.17677669529663687f
#define NN    (NRES * NRES)
#define MSPLIT 4

#define GEMM_BLKS 368       // 16 row-tiles x 23 col-tiles of the proj GEMM
#define PB_TILES  8
#define PB_BLKS   (NN / (64 * PB_TILES))      // 2048
#define MEGA_SMEM (3 * 64 * 128 * 4)          // 3 x 32KB pair buffers

// ---------------- scratch (device globals: allocation-free) ----------------
__device__ float g_proj[NRES * WPROJ];
__device__ float g_Fq[NH * NRES * FDIM];
__device__ float g_Fk[NH * NRES * FDIM];
__device__ float g_Vs[NH * NRES * CHD];
__device__ float g_rowt[NH * NRES];
__device__ float g_colt[NH * NRES];
__device__ __half g_biash[(size_t)NH * NN];   // 25 MB fp16 bias
__device__ float g_pM[MSPLIT * NH * NRES];
__device__ float g_pS[MSPLIT * NH * NRES];
__device__ float g_pO[(size_t)MSPLIT * NH * NRES * CHD];
__device__ float g_wt[NRES * CDIM];
__device__ float g_x[NRES * CDIM];

// ---------------- helpers ----------------
__device__ __forceinline__ uint32_t f2tf(float x) {
    uint32_t u;
    asm("cvt.rna.tf32.f32 %0, %1;" : "=r"(u) : "f"(x));
    return u;
}

__device__ __forceinline__ void mma8(float c[4],
                                     uint32_t a0, uint32_t a1, uint32_t a2, uint32_t a3,
                                     uint32_t b0, uint32_t b1) {
    asm volatile(
        "mma.sync.aligned.m16n8k8.row.col.f32.tf32.tf32.f32 "
        "{%0,%1,%2,%3}, {%4,%5,%6,%7}, {%8,%9}, {%0,%1,%2,%3};"
        : "+f"(c[0]), "+f"(c[1]), "+f"(c[2]), "+f"(c[3])
        : "r"(a0), "r"(a1), "r"(a2), "r"(a3), "r"(b0), "r"(b1));
}

__device__ __forceinline__ void cp16(uint32_t sa, const void* g) {
    asm volatile("cp.async.cg.shared.global [%0], [%1], 16;" :: "r"(sa), "l"(g));
}

__device__ __forceinline__ float projbias(int j,
        const float* bq, const float* bk, const float* bv,
        const float* bpq, const float* bpk) {
    if (j < 384)  return bq[j];
    if (j < 768)  return bk[j - 384];
    if (j < 1152) return bv[j - 768];
    if (j < 1296) return bpq[j - 1152];
    return bpk[j - 1296];
}

// ============ K1: MEGA — proj GEMM blocks + pairbias blocks in one grid =====
__global__ void __launch_bounds__(128) k_mega(
    const float* __restrict__ pair, const float* __restrict__ Wp,
    const float* __restrict__ bp, const float* __restrict__ single,
    const float* __restrict__ Wq, const float* __restrict__ Wk,
    const float* __restrict__ Wv, const float* __restrict__ Wpq,
    const float* __restrict__ Wpk,
    const float* __restrict__ bq, const float* __restrict__ bk,
    const float* __restrict__ bv, const float* __restrict__ bpq,
    const float* __restrict__ bpk) {
    extern __shared__ float smem[];
    int tid = threadIdx.x, lane = tid & 31, w = tid >> 5;
    int g = lane >> 2, t = lane & 3;

    if (blockIdx.x < GEMM_BLKS) {
        // ---------------- projection GEMM: g_proj = single @ Wall + ball ----
        float* As = smem;            // 64 x 36
        float* Bs = As + 64 * 36;    // 32 x 72
        int bid = blockIdx.x;
        int n0 = (bid % 23) * 64, m0 = (bid / 23) * 64;
        int wy = w >> 1, wx = w & 1;

        float c[2][4][4];
#pragma unroll
        for (int s = 0; s < 2; s++)
#pragma unroll
            for (int i = 0; i < 4; i++)
#pragma unroll
                for (int j = 0; j < 4; j++) c[s][i][j] = 0.f;

        for (int kc = 0; kc < CDIM; kc += 32) {
#pragma unroll
            for (int it = 0; it < 4; it++) {
                int idx = tid + it * 128;
                int r = idx >> 3, c4 = (idx & 7) * 4;
                float4 v = *(const float4*)(single + (size_t)(m0 + r) * CDIM + kc + c4);
                *(float4*)(As + r * 36 + c4) = v;
            }
#pragma unroll
            for (int it = 0; it < 4; it++) {
                int idx = tid + it * 128;
                int r = idx >> 4, c4 = (idx & 15) * 4;
                int col = n0 + c4;
                float4 v = make_float4(0.f, 0.f, 0.f, 0.f);
                if (col < WPROJ) {
                    const float* W; int cj, wdt;
                    if (col < 384)       { W = Wq;  cj = col;        wdt = 384; }
                    else if (col < 768)  { W = Wk;  cj = col - 384;  wdt = 384; }
                    else if (col < 1152) { W = Wv;  cj = col - 768;  wdt = 384; }
                    else if (col < 1296) { W = Wpq; cj = col - 1152; wdt = 144; }
                    else                 { W = Wpk; cj = col - 1296; wdt = 144; }
                    v = *(const float4*)(W + (size_t)(kc + r) * wdt + cj);
                }
                *(float4*)(Bs + r * 72 + c4) = v;
            }
            __syncthreads();
#pragma unroll
            for (int ks = 0; ks < 4; ks++) {
                uint32_t a[2][4];
#pragma unroll
                for (int s = 0; s < 2; s++) {
                    int rb = wy * 32 + s * 16;
                    a[s][0] = f2tf(As[(rb + g) * 36 + ks * 8 + t]);
                    a[s][1] = f2tf(As[(rb + g + 8) * 36 + ks * 8 + t]);
                    a[s][2] = f2tf(As[(rb + g) * 36 + ks * 8 + t + 4]);
                    a[s][3] = f2tf(As[(rb + g + 8) * 36 + ks * 8 + t + 4]);
                }
#pragma unroll
                for (int nb = 0; nb < 4; nb++) {
                    uint32_t b0 = f2tf(Bs[(ks * 8 + t) * 72 + wx * 32 + nb * 8 + g]);
                    uint32_t b1 = f2tf(Bs[(ks * 8 + t + 4) * 72 + wx * 32 + nb * 8 + g]);
                    mma8(c[0][nb], a[0][0], a[0][1], a[0][2], a[0][3], b0, b1);
                    mma8(c[1][nb], a[1][0], a[1][1], a[1][2], a[1][3], b0, b1);
                }
            }
            __syncthreads();
        }
#pragma unroll
        for (int s = 0; s < 2; s++)
#pragma unroll
            for (int nb = 0; nb < 4; nb++)
#pragma unroll
                for (int rr = 0; rr < 4; rr++) {
                    int row = m0 + wy * 32 + s * 16 + g + ((rr & 2) ? 8 : 0);
                    int col = n0 + wx * 32 + nb * 8 + 2 * t + (rr & 1);
                    if (col < WPROJ) {
                        g_proj[(size_t)row * WPROJ + col] =
                            c[s][nb][rr] + projbias(col, bq, bk, bv, bpq, bpk);
                    }
                }
        return;
    }

    // ---------------- pairbias path: 8 tiles of 64 rows, 3-deep pipeline ----
    float* Ps = smem;   // 3 x [64][128], swizzled
    size_t rowbase = (size_t)(blockIdx.x - GEMM_BLKS) * (64 * PB_TILES);

    uint32_t bf[16][4];
#pragma unroll
    for (int ks = 0; ks < 16; ks++)
#pragma unroll
        for (int nb = 0; nb < 2; nb++) {
            int h = nb * 8 + g;
            float b0 = (h < 12) ? Wp[(ks * 8 + t) * 12 + h] : 0.f;
            float b1 = (h < 12) ? Wp[(ks * 8 + t + 4) * 12 + h] : 0.f;
            bf[ks][nb * 2 + 0] = f2tf(b0);
            bf[ks][nb * 2 + 1] = f2tf(b1);
        }
    float bpv[2][2];
#pragma unroll
    for (int nb = 0; nb < 2; nb++)
#pragma unroll
        for (int par = 0; par < 2; par++) {
            int h = nb * 8 + 2 * t + par;
            bpv[nb][par] = (h < 12) ? bp[h] : 0.f;
        }

    const float4* gsrc = (const float4*)(pair + rowbase * DPAIR);

    auto stage = [&](int tl, int buf) {
        const float4* src = gsrc + (size_t)tl * 2048;
        float* dst = Ps + buf * (64 * 128);
#pragma unroll
        for (int it = 0; it < 16; it++) {
            int idx = tid + it * 128;
            int r = idx >> 5, c4 = idx & 31;
            uint32_t sa = (uint32_t)__cvta_generic_to_shared(
                dst + r * 128 + ((c4 ^ (r & 7)) << 2));
            cp16(sa, src + idx);
        }
        asm volatile("cp.async.commit_group;");
    };

    stage(0, 0);
    stage(1, 1);
    int rbase = w * 16;
    for (int tl = 0; tl < PB_TILES; tl++) {
        if (tl + 1 < PB_TILES) {
            asm volatile("cp.async.wait_group 1;");
        } else {
            asm volatile("cp.async.wait_group 0;");
        }
        __syncthreads();
        if (tl + 2 < PB_TILES) stage(tl + 2, (tl + 2) % 3);

        const float* P = Ps + (tl % 3) * (64 * 128);
        float c[2][4];
#pragma unroll
        for (int i = 0; i < 2; i++)
#pragma unroll
            for (int j = 0; j < 4; j++) c[i][j] = 0.f;
#pragma unroll
        for (int ks = 0; ks < 16; ks++) {
            const float* r0p = P + (rbase + g) * 128;
            const float* r8p = P + (rbase + g + 8) * 128;
            int e0 = (((2 * ks) ^ g) << 2) + t;
            int e1 = (((2 * ks + 1) ^ g) << 2) + t;
            uint32_t a0 = f2tf(r0p[e0]);
            uint32_t a1 = f2tf(r8p[e0]);
            uint32_t a2 = f2tf(r0p[e1]);
            uint32_t a3 = f2tf(r8p[e1]);
            mma8(c[0], a0, a1, a2, a3, bf[ks][0], bf[ks][1]);
            mma8(c[1], a0, a1, a2, a3, bf[ks][2], bf[ks][3]);
        }
        size_t trow = rowbase + (size_t)tl * 64 + rbase + g;
#pragma unroll
        for (int nb = 0; nb < 2; nb++)
#pragma unroll
            for (int rr = 0; rr < 4; rr++) {
                int h = nb * 8 + 2 * t + (rr & 1);
                if (h < 12) {
                    size_t row = trow + ((rr & 2) ? 8 : 0);
                    g_biash[(size_t)h * NN + row] =
                        __float2half(c[nb][rr] + bpv[nb][rr & 1]);
                }
            }
    }
}

// ---------------- K1b: rotate points, build per-head features ----------------
__global__ void k_feat(const float* __restrict__ rot) {
    int n = blockIdx.x;
    int t = threadIdx.x;  // 128 threads
    __shared__ float R[9];
    __shared__ float sq[NH], sk[NH];
    if (t < 9)  R[t] = rot[n * 9 + t];
    if (t < NH) { sq[t] = 0.f; sk[t] = 0.f; }
    __syncthreads();
    const float* pr = g_proj + (size_t)n * WPROJ;
    for (int idx = t; idx < PDIM; idx += 128) {
        int h = idx / 12, rem = idx % 12, p = rem / 3, j = rem % 3;
        const float* pq = pr + 1152 + (h * NPTS + p) * 3;
        const float* pk = pr + 1296 + (h * NPTS + p) * 3;
        float qg = pq[0] * R[j] + pq[1] * R[3 + j] + pq[2] * R[6 + j];
        float kg = pk[0] * R[j] + pk[1] * R[3 + j] + pk[2] * R[6 + j];
        g_Fq[((size_t)h * NRES + n) * FDIM + 32 + p * 3 + j] = qg;
        g_Fk[((size_t)h * NRES + n) * FDIM + 32 + p * 3 + j] = kg;
        atomicAdd(&sq[h], qg * qg);
        atomicAdd(&sk[h], kg * kg);
    }
    for (int c = t; c < CDIM; c += 128) {
        int h = c >> 5, cc = c & 31;
        g_Fq[((size_t)h * NRES + n) * FDIM + cc] = pr[c];
        g_Fk[((size_t)h * NRES + n) * FDIM + cc] = pr[384 + c];
        g_Vs[((size_t)h * NRES + n) * CHD + cc] = pr[768 + c];
    }
    if (t < NH * 4) {
        int h = t >> 2;
        g_Fq[((size_t)h * NRES + n) * FDIM + 44 + (t & 3)] = 0.f;
        g_Fk[((size_t)h * NRES + n) * FDIM + 44 + (t & 3)] = 0.f;
    }
    __syncthreads();
    if (t < NH) {
        g_rowt[t * NRES + n] = sq[t];
        g_colt[t * NRES + n] = sk[t];
    }
}

// ---------------- K2: split-m flash attention ------------------------------
__global__ void __launch_bounds__(128) k_attn() {
    __shared__ float Fks[64 * 52];
    __shared__ float Vsm[64 * 40];
    __shared__ float Psm[4 * 16 * 68];
    __shared__ float cts[64];
    int h = blockIdx.y;
    int n0 = blockIdx.x * 64;
    int sp = blockIdx.z;
    int tid = threadIdx.x, lane = tid & 31, w = tid >> 5;
    int g = lane >> 2, t = lane & 3;
    int row0 = n0 + w * 16 + g;
    int row8 = row0 + 8;

    uint32_t afr[6][4];
#pragma unroll
    for (int ks = 0; ks < 6; ks++) {
        afr[ks][0] = f2tf(g_Fq[((size_t)h * NRES + row0) * FDIM + ks * 8 + t]);
        afr[ks][1] = f2tf(g_Fq[((size_t)h * NRES + row8) * FDIM + ks * 8 + t]);
        afr[ks][2] = f2tf(g_Fq[((size_t)h * NRES + row0) * FDIM + ks * 8 + t + 4]);
        afr[ks][3] = f2tf(g_Fq[((size_t)h * NRES + row8) * FDIM + ks * 8 + t + 4]);
    }
    float rt0 = -0.5f * SCALEF * g_rowt[h * NRES + row0];
    float rt8 = -0.5f * SCALEF * g_rowt[h * NRES + row8];

    float o[4][4];
#pragma unroll
    for (int i = 0; i < 4; i++)
#pragma unroll
        for (int j = 0; j < 4; j++) o[i][j] = 0.f;
    float M0 = -1e30f, M8 = -1e30f, S0 = 0.f, S8 = 0.f;
    float* Pw = Psm + w * 16 * 68;
    const __half* bptr = g_biash + (size_t)h * NN;

    for (int mt = sp * 4; mt < sp * 4 + 4; mt++) {
        int m0 = mt * 64;
#pragma unroll
        for (int it = 0; it < 6; it++) {
            int idx = tid + it * 128;
            int r = idx / 12, c4 = (idx % 12) * 4;
            float4 v = *(const float4*)(g_Fk + ((size_t)h * NRES + m0 + r) * FDIM + c4);
            uint4 u = make_uint4(f2tf(v.x), f2tf(v.y), f2tf(v.z), f2tf(v.w));
            *(uint4*)(Fks + r * 52 + c4) = u;
        }
#pragma unroll
        for (int it = 0; it < 4; it++) {
            int idx = tid + it * 128;
            int r = idx >> 3, c4 = (idx & 7) * 4;
            float4 v = *(const float4*)(g_Vs + ((size_t)h * NRES + m0 + r) * CHD + c4);
            uint4 u = make_uint4(f2tf(v.x), f2tf(v.y), f2tf(v.z), f2tf(v.w));
            *(uint4*)(Vsm + r * 40 + c4) = u;
        }
        if (tid < 64) cts[tid] = -0.5f * SCALEF * g_colt[h * NRES + m0 + tid];
        __syncthreads();

        float s[8][4];
#pragma unroll
        for (int nb = 0; nb < 8; nb++) {
#pragma unroll
            for (int j = 0; j < 4; j++) s[nb][j] = 0.f;
#pragma unroll
            for (int ks = 0; ks < 6; ks++) {
                uint32_t b0 = __float_as_uint(Fks[(nb * 8 + g) * 52 + ks * 8 + t]);
                uint32_t b1 = __float_as_uint(Fks[(nb * 8 + g) * 52 + ks * 8 + t + 4]);
                mma8(s[nb], afr[ks][0], afr[ks][1], afr[ks][2], afr[ks][3], b0, b1);
            }
        }
        const __half2* bh0 = (const __half2*)(bptr + (size_t)row0 * NRES + m0);
        const __half2* bh8 = (const __half2*)(bptr + (size_t)row8 * NRES + m0);
#pragma unroll
        for (int nb = 0; nb < 8; nb++) {
            int cA = nb * 8 + 2 * t;
            float2 b0f = __half22float2(bh0[cA >> 1]);
            float2 b8f = __half22float2(bh8[cA >> 1]);
            s[nb][0] = SCALEF * s[nb][0] + rt0 + cts[cA]     + b0f.x;
            s[nb][1] = SCALEF * s[nb][1] + rt0 + cts[cA + 1] + b0f.y;
            s[nb][2] = SCALEF * s[nb][2] + rt8 + cts[cA]     + b8f.x;
            s[nb][3] = SCALEF * s[nb][3] + rt8 + cts[cA + 1] + b8f.y;
        }
        float m0l = -1e30f, m8l = -1e30f;
#pragma unroll
        for (int nb = 0; nb < 8; nb++) {
            m0l = fmaxf(m0l, fmaxf(s[nb][0], s[nb][1]));
            m8l = fmaxf(m8l, fmaxf(s[nb][2], s[nb][3]));
        }
        m0l = fmaxf(m0l, __shfl_xor_sync(0xffffffffu, m0l, 1));
        m0l = fmaxf(m0l, __shfl_xor_sync(0xffffffffu, m0l, 2));
        m8l = fmaxf(m8l, __shfl_xor_sync(0xffffffffu, m8l, 1));
        m8l = fmaxf(m8l, __shfl_xor_sync(0xffffffffu, m8l, 2));
        float Mn0 = fmaxf(M0, m0l), Mn8 = fmaxf(M8, m8l);
        float al0 = __expf(M0 - Mn0), al8 = __expf(M8 - Mn8);
        M0 = Mn0; M8 = Mn8;

        float ls0 = 0.f, ls8 = 0.f;
#pragma unroll
        for (int nb = 0; nb < 8; nb++) {
            int cA = nb * 8 + 2 * t, cB = cA + 1;
            float p00 = __expf(s[nb][0] - Mn0);
            float p01 = __expf(s[nb][1] - Mn0);
            float p10 = __expf(s[nb][2] - Mn8);
            float p11 = __expf(s[nb][3] - Mn8);
            ls0 += p00 + p01; ls8 += p10 + p11;
            Pw[g * 68 + cA] = __uint_as_float(f2tf(p00));
            Pw[g * 68 + cB] = __uint_as_float(f2tf(p01));
            Pw[(g + 8) * 68 + cA] = __uint_as_float(f2tf(p10));
            Pw[(g + 8) * 68 + cB] = __uint_as_float(f2tf(p11));
        }
        ls0 += __shfl_xor_sync(0xffffffffu, ls0, 1);
        ls0 += __shfl_xor_sync(0xffffffffu, ls0, 2);
        ls8 += __shfl_xor_sync(0xffffffffu, ls8, 1);
        ls8 += __shfl_xor_sync(0xffffffffu, ls8, 2);
        S0 = S0 * al0 + ls0;
        S8 = S8 * al8 + ls8;
#pragma unroll
        for (int nb = 0; nb < 4; nb++) {
            o[nb][0] *= al0; o[nb][1] *= al0;
            o[nb][2] *= al8; o[nb][3] *= al8;
        }
        __syncwarp();
#pragma unroll
        for (int ks = 0; ks < 8; ks++) {
            uint32_t a0 = __float_as_uint(Pw[g * 68 + ks * 8 + t]);
            uint32_t a1 = __float_as_uint(Pw[(g + 8) * 68 + ks * 8 + t]);
            uint32_t a2 = __float_as_uint(Pw[g * 68 + ks * 8 + t + 4]);
            uint32_t a3 = __float_as_uint(Pw[(g + 8) * 68 + ks * 8 + t + 4]);
#pragma unroll
            for (int nb = 0; nb < 4; nb++) {
                uint32_t b0 = __float_as_uint(Vsm[(ks * 8 + t) * 40 + nb * 8 + g]);
                uint32_t b1 = __float_as_uint(Vsm[(ks * 8 + t + 4) * 40 + nb * 8 + g]);
                mma8(o[nb], a0, a1, a2, a3, b0, b1);
            }
        }
        __syncthreads();
    }
    int pidx0 = (sp * NH + h) * NRES + row0;
    int pidx8 = pidx0 + 8;
    if (t == 0) {
        g_pM[pidx0] = M0; g_pS[pidx0] = S0;
        g_pM[pidx8] = M8; g_pS[pidx8] = S8;
    }
#pragma unroll
    for (int nb = 0; nb < 4; nb++) {
        int c0 = nb * 8 + 2 * t;
        g_pO[(size_t)pidx0 * CHD + c0]     = o[nb][0];
        g_pO[(size_t)pidx0 * CHD + c0 + 1] = o[nb][1];
        g_pO[(size_t)pidx8 * CHD + c0]     = o[nb][2];
        g_pO[(size_t)pidx8 * CHD + c0 + 1] = o[nb][3];
    }
}

// ---------------- K2b: merge m-split partials -------------------------------
__global__ void __launch_bounds__(256) k_merge() {
    int w = threadIdx.x >> 5, lane = threadIdx.x & 31;
    int pi = blockIdx.x * 8 + w;           // 12288 (n,h) pairs
    int n = pi / NH, h = pi % NH;
    float Ms[MSPLIT], Ss[MSPLIT], Os[MSPLIT];
    float Mx = -1e30f;
#pragma unroll
    for (int s = 0; s < MSPLIT; s++) {
        int idx = (s * NH + h) * NRES + n;
        Ms[s] = g_pM[idx];
        Ss[s] = g_pS[idx];
        Os[s] = g_pO[(size_t)idx * CHD + lane];
        Mx = fmaxf(Mx, Ms[s]);
    }
    float den = 0.f, num = 0.f;
#pragma unroll
    for (int s = 0; s < MSPLIT; s++) {
        float wgt = __expf(Ms[s] - Mx);
        den += wgt * Ss[s];
        num += wgt * Os[s];
    }
    g_wt[(size_t)n * CDIM + h * 32 + lane] = num / den;
}

// ---------------- K3: out projection (256-thr generic tf32 GEMM) ------------
__global__ void __launch_bounds__(256) k_gemm(
    const float* __restrict__ A, const float* __restrict__ B,
    const float* __restrict__ bias, const float* __restrict__ resid,
    float* __restrict__ out, int M, int Nn, int K) {
    __shared__ float As[64 * 36];
    __shared__ float Bs[32 * 72];
    int tid = threadIdx.x;
    int lane = tid & 31, wid = tid >> 5;
    int wy = wid >> 1, wx = wid & 1;
    int g = lane >> 2, t = lane & 3;
    int n0 = blockIdx.x * 64, m0 = blockIdx.y * 64;

    float c[4][4];
#pragma unroll
    for (int i = 0; i < 4; i++)
#pragma unroll
        for (int j = 0; j < 4; j++) c[i][j] = 0.f;

    for (int kc = 0; kc < K; kc += 32) {
#pragma unroll
        for (int it = 0; it < 2; it++) {
            int idx = tid + it * 256;
            int r = idx >> 3, c4 = (idx & 7) * 4;
            float4 v = *(const float4*)(A + (size_t)(m0 + r) * K + kc + c4);
            *(float4*)(As + r * 36 + c4) = v;
        }
#pragma unroll
        for (int it = 0; it < 2; it++) {
            int idx = tid + it * 256;
            int r = idx >> 4, c4 = (idx & 15) * 4;
            int col = n0 + c4;
            float4 v = make_float4(0.f, 0.f, 0.f, 0.f);
            if (col < Nn) v = *(const float4*)(B + (size_t)(kc + r) * Nn + col);
            *(float4*)(Bs + r * 72 + c4) = v;
        }
        __syncthreads();
#pragma unroll
        for (int ks = 0; ks < 4; ks++) {
            uint32_t a0 = f2tf(As[(wy * 16 + g) * 36 + ks * 8 + t]);
            uint32_t a1 = f2tf(As[(wy * 16 + g + 8) * 36 + ks * 8 + t]);
            uint32_t a2 = f2tf(As[(wy * 16 + g) * 36 + ks * 8 + t + 4]);
            uint32_t a3 = f2tf(As[(wy * 16 + g + 8) * 36 + ks * 8 + t + 4]);
#pragma unroll
            for (int nb = 0; nb < 4; nb++) {
                uint32_t b0 = f2tf(Bs[(ks * 8 + t) * 72 + wx * 32 + nb * 8 + g]);
                uint32_t b1 = f2tf(Bs[(ks * 8 + t + 4) * 72 + wx * 32 + nb * 8 + g]);
                mma8(c[nb], a0, a1, a2, a3, b0, b1);
            }
        }
        __syncthreads();
    }
#pragma unroll
    for (int nb = 0; nb < 4; nb++)
#pragma unroll
        for (int rr = 0; rr < 4; rr++) {
            int row = m0 + wy * 16 + g + ((rr & 2) ? 8 : 0);
            int col = n0 + wx * 32 + nb * 8 + 2 * t + (rr & 1);
            if (col < Nn) {
                float v = c[nb][rr] + bias[col];
                if (resid) v += resid[(size_t)row * Nn + col];
                out[(size_t)row * Nn + col] = v;
            }
        }
}

// ---------------- K4: layernorm ----------------
__global__ void k_ln(const float* __restrict__ gamma, const float* __restrict__ beta,
                     float* __restrict__ out) {
    int n = blockIdx.x, t = threadIdx.x;  // 128 threads
    int lane = t & 31, w = t >> 5;
    __shared__ float r1[4], r2[4];
    const float* x = g_x + (size_t)n * CDIM;
    float v0 = x[t], v1 = x[t + 128], v2 = x[t + 256];
    float s = v0 + v1 + v2;
#pragma unroll
    for (int off = 16; off; off >>= 1) s += __shfl_xor_sync(0xffffffffu, s, off);
    if (lane == 0) r1[w] = s;
    __syncthreads();
    float mean = (r1[0] + r1[1] + r1[2] + r1[3]) * (1.f / CDIM);
    float d0 = v0 - mean, d1 = v1 - mean, d2 = v2 - mean;
    float ss = d0 * d0 + d1 * d1 + d2 * d2;
#pragma unroll
    for (int off = 16; off; off >>= 1) ss += __shfl_xor_sync(0xffffffffu, ss, off);
    if (lane == 0) r2[w] = ss;
    __syncthreads();
    float var = (r2[0] + r2[1] + r2[2] + r2[3]) * (1.f / CDIM);
    float rs = rsqrtf(var + 1e-5f);
    out[(size_t)n * CDIM + t]       = d0 * rs * gamma[t] + beta[t];
    out[(size_t)n * CDIM + t + 128] = d1 * rs * gamma[t + 128] + beta[t + 128];
    out[(size_t)n * CDIM + t + 256] = d2 * rs * gamma[t + 256] + beta[t + 256];
}

// ---------------- launch (single stream — graph-capture safe) ----------------
extern "C" void kernel_launch(void* const* d_in, const int* in_sizes, int n_in,
                              void* d_out, int out_size) {
    (void)in_sizes; (void)n_in; (void)out_size;
    const float* single = (const float*)d_in[0];
    const float* pair   = (const float*)d_in[1];
    const float* rot    = (const float*)d_in[2];
    const float* Wq  = (const float*)d_in[4];
    const float* bq  = (const float*)d_in[5];
    const float* Wk  = (const float*)d_in[6];
    const float* bk  = (const float*)d_in[7];
    const float* Wv  = (const float*)d_in[8];
    const float* bv  = (const float*)d_in[9];
    const float* Wpair = (const float*)d_in[10];
    const float* bpair = (const float*)d_in[11];
    const float* Wpq = (const float*)d_in[12];
    const float* bpq = (const float*)d_in[13];
    const float* Wpk = (const float*)d_in[14];
    const float* bpk = (const float*)d_in[15];
    const float* Wout = (const float*)d_in[16];
    const float* bout = (const float*)d_in[17];
    const float* gamma = (const float*)d_in[18];
    const float* beta  = (const float*)d_in[19];

    float *pwt, *px;
    cudaGetSymbolAddress((void**)&pwt, g_wt);
    cudaGetSymbolAddress((void**)&px,  g_x);

    static bool attr_done = false;
    if (!attr_done) {
        cudaFuncSetAttribute(k_mega,
            cudaFuncAttributeMaxDynamicSharedMemorySize, MEGA_SMEM);
        attr_done = true;
    }

    // K1: mega — proj GEMM (368 blocks) interleaved with pairbias (2048 blocks)
    k_mega<<<GEMM_BLKS + PB_BLKS, 128, MEGA_SMEM>>>(
        pair, Wpair, bpair, single,
        Wq, Wk, Wv, Wpq, Wpk, bq, bk, bv, bpq, bpk);
    // K1b: rotations + features
    k_feat<<<NRES, 128>>>(rot);
    // K2: split-m fused attention + merge
    k_attn<<<dim3(16, NH, MSPLIT), 128>>>();
    k_merge<<<NRES * NH / 8, 256>>>();
    // K3: out projection + residual
    k_gemm<<<dim3(6, 16), 256>>>(pwt, Wout, bout, single, px, NRES, CDIM, CDIM);
    // K4: layernorm -> output
    k_ln<<<NRES, 128>>>(gamma, beta, (float*)d_out);
}